// round 6
// baseline (speedup 1.0000x reference)
#include <cuda_runtime.h>

// FINAL. Reference math collapses exactly:
//   p1 has feature dim 1  ->  mu == p1 (exact, mean over a singleton axis)
//   (p1 - mu) == 0 exactly -> var == 0 exactly
//   out = 0/sqrt(eps) * ln_weight + ln_bias = ln_bias  (for ANY x/params/ln_weight)
// So out[b] = ln_bias[0] for all b. We read ln_bias from device memory to stay
// correct for arbitrary bias values.
//
// Measured floor: wall 4.576 us is invariant across launch shapes (graph-replay
// overhead dominated); we pin the shape with the best kernel-node time
// (grid=2 x 256, node 3.328 us in R3).

__global__ __launch_bounds__(256, 1)
void QuantumGate_65481071410733_kernel(const float* __restrict__ ln_bias,
                                       float* __restrict__ out,
                                       int n) {
    int i = blockIdx.x * blockDim.x + threadIdx.x;
    if (i < n) {
        out[i] = __ldg(ln_bias);
    }
}

extern "C" void kernel_launch(void* const* d_in, const int* in_sizes, int n_in,
                              void* d_out, int out_size) {
    // Input order per metadata: x, params, ln_weight, ln_bias
    const float* ln_bias = (const float*)d_in[3];
    float* out = (float*)d_out;
    int n = out_size;  // 512
    QuantumGate_65481071410733_kernel<<<(n + 255) / 256, 256>>>(ln_bias, out, n);
}